// round 5
// baseline (speedup 1.0000x reference)
#include <cuda_runtime.h>
#include <cstdint>

#define NROWS 4096
#define AADDR 32768
#define FD    160
#define CDIM  10

#define BM 128
#define BN 64
#define SLICES 16
#define APS (AADDR / SLICES)     // 2048
#define NCH (APS / BN)           // 32
#define THREADS 512

// Row stride 164 floats (656 B): 164 % 32 == 4 -> every 8-row ldmatrix phase
// covers all 32 banks (conflict-free).
#define SAK 164
#define A_BYTES   (BM * SAK * 4)          // 83968
#define B_BUF     (BN * SAK * 4)          // 41984
#define SM_A   0
#define SM_B   (SM_A + A_BYTES)           // 83968
#define SM_M   (SM_B + 2 * B_BUF)         // 167936 (2 x 2560)
#define SM_Y2  (SM_M + 2 * 2560)          // 173056 (2048 f32)
#define SM_X2  (SM_Y2 + 8192)             // 181248 (128 f32)
#define SMEM_TOTAL (SM_X2 + 512)          // 181760

#define KK 1.3115409462626940f   // log2(e)/1.1
#define CK 20.984655140203105f   // 16*log2(e)/1.1

__device__ float g_y2[AADDR];
__device__ float g_part[SLICES * 4 * NROWS * 12];

// ---------------- helpers ----------------
__device__ __forceinline__ uint32_t smem_u32(const void* p) {
    uint32_t a;
    asm("{ .reg .u64 t; cvta.to.shared.u64 t, %1; cvt.u32.u64 %0, t; }" : "=r"(a) : "l"(p));
    return a;
}
__device__ __forceinline__ float ex2f(float x) {
    float y; asm("ex2.approx.f32 %0, %1;" : "=f"(y) : "f"(x)); return y;
}
__device__ __forceinline__ float sqrt_ap(float x) {
    float y; asm("sqrt.approx.f32 %0, %1;" : "=f"(y) : "f"(x)); return y;
}
__device__ __forceinline__ unsigned long long dup2(float v) {
    unsigned long long r; asm("mov.b64 %0, {%1, %1};" : "=l"(r) : "f"(v)); return r;
}
__device__ __forceinline__ void fma2(unsigned long long& d, unsigned long long a, unsigned long long b) {
    asm("fma.rn.f32x2 %0, %1, %2, %0;" : "+l"(d) : "l"(a), "l"(b));
}
__device__ __forceinline__ float2 unpk(unsigned long long v) {
    float2 r; asm("mov.b64 {%0, %1}, %2;" : "=f"(r.x), "=f"(r.y) : "l"(v)); return r;
}
__device__ __forceinline__ void cp16(uint32_t dst, const void* src) {
    asm volatile("cp.async.cg.shared.global [%0], [%1], 16;" :: "r"(dst), "l"(src));
}
__device__ __forceinline__ void cp_commit() { asm volatile("cp.async.commit_group;" ::: "memory"); }
__device__ __forceinline__ void cp_wait1()  { asm volatile("cp.async.wait_group 1;" ::: "memory"); }
__device__ __forceinline__ void cp_wait0()  { asm volatile("cp.async.wait_group 0;" ::: "memory"); }

__device__ __forceinline__ void ldsm4(uint32_t* r, uint32_t addr) {
    asm volatile("ldmatrix.sync.aligned.m8n8.x4.shared.b16 {%0,%1,%2,%3}, [%4];"
                 : "=r"(r[0]), "=r"(r[1]), "=r"(r[2]), "=r"(r[3]) : "r"(addr));
}

__device__ __forceinline__ void mma8(float* c, const uint32_t* a, const uint32_t* b) {
    asm volatile("mma.sync.aligned.m16n8k8.row.col.f32.tf32.tf32.f32 "
                 "{%0,%1,%2,%3}, {%4,%5,%6,%7}, {%8,%9}, {%0,%1,%2,%3};"
                 : "+f"(c[0]), "+f"(c[1]), "+f"(c[2]), "+f"(c[3])
                 : "r"(a[0]), "r"(a[1]), "r"(a[2]), "r"(a[3]),
                   "r"(b[0]), "r"(b[1]));
}

// ---------------- prep: ||Address||^2 ----------------
__global__ void prep_y2_kernel(const float* __restrict__ Ad) {
    int row = (blockIdx.x * 256 + threadIdx.x) >> 5;
    int lane = threadIdx.x & 31;
    const float4* p = (const float4*)(Ad + (size_t)row * FD);
    float4 v = p[lane];
    float s = v.x * v.x + v.y * v.y + v.z * v.z + v.w * v.w;
    if (lane < 8) {
        float4 u = p[32 + lane];
        s += u.x * u.x + u.y * u.y + u.z * u.z + u.w * u.w;
    }
    #pragma unroll
    for (int o = 16; o; o >>= 1) s += __shfl_xor_sync(0xffffffffu, s, o);
    if (lane == 0) g_y2[row] = s;
}

// ---------------- chunk loader (cp.async) ----------------
__device__ __forceinline__ void issue_chunk(int c, int t, uint32_t sbase, int aSlice,
                                            const float* __restrict__ Ad,
                                            const float* __restrict__ M) {
    int buf = c & 1;
    int a0 = aSlice + c * BN;
    int r = t >> 3, q = t & 7;
    const char* src = (const char*)(Ad + (size_t)(a0 + r) * FD);
    uint32_t bdst = sbase + SM_B + buf * B_BUF + r * (SAK * 4);
    #pragma unroll
    for (int i = 0; i < 5; i++) {
        int j = q + 8 * i;                        // float4 index 0..39
        cp16(bdst + j * 16, src + j * 16);
    }
    if (t < (BN * CDIM) / 4)
        cp16(sbase + SM_M + buf * 2560 + t * 16,
             (const char*)(M + (size_t)a0 * CDIM) + t * 16);
}

// ---------------- main fused kernel ----------------
__global__ __launch_bounds__(THREADS, 1)
void fused_mma_kernel(const float* __restrict__ X,
                      const float* __restrict__ Ad,
                      const float* __restrict__ M) {
    extern __shared__ __align__(1024) char sm[];
    uint32_t sbase = smem_u32(sm);
    const float* y2s = (const float*)(sm + SM_Y2);

    int t = threadIdx.x;
    int wid = t >> 5, lane = t & 31;
    int g = lane >> 2, tig = lane & 3;
    int wm = wid & 3, wn = wid >> 2;      // 4 x 4 warp grid
    int m0 = wm * 32, n0 = wn * 16;
    int rowBase = blockIdx.x * BM;
    int aSlice = blockIdx.y * APS;

    // stage A tile: 128 rows x 40 float4
    {
        int r = t >> 2;
        const char* src = (const char*)(X + (size_t)(rowBase + r) * FD);
        uint32_t adst = sbase + SM_A + r * (SAK * 4);
        #pragma unroll
        for (int i = 0; i < 10; i++) {
            int j = (t & 3) + 4 * i;
            cp16(adst + j * 16, src + j * 16);
        }
    }
    // stage y2 slice: 512 float4
    cp16(sbase + SM_Y2 + t * 16, (const char*)(g_y2 + aSlice) + t * 16);
    // x2 per row (exact fp32)
    if (t < BM) {
        const float4* p = (const float4*)(X + (size_t)(rowBase + t) * FD);
        float s = 0.f;
        #pragma unroll
        for (int i = 0; i < FD / 4; i++) {
            float4 v = p[i];
            s = fmaf(v.x, v.x, s); s = fmaf(v.y, v.y, s);
            s = fmaf(v.z, v.z, s); s = fmaf(v.w, v.w, s);
        }
        ((float*)(sm + SM_X2))[t] = s;
    }
    issue_chunk(0, t, sbase, aSlice, Ad, M);
    cp_commit();
    cp_wait0();
    __syncthreads();

    float x2r[4];
    #pragma unroll
    for (int i = 0; i < 4; i++) x2r[i] = ((const float*)(sm + SM_X2))[m0 + g + 8 * i];

    // ldmatrix per-lane base addresses
    int tr = lane & 7, tt = lane >> 3;
    // A x4: tile0 m+0..7 @k0 | tile1 m+8..15 @k0 | tile2 m+0..7 @k0+4 | tile3 m+8..15 @k0+4
    uint32_t aBase0 = sbase + SM_A +
        (((m0 + (tt & 1) * 8 + tr) * SAK) + (tt >> 1) * 4) * 4;
    uint32_t aBase1 = aBase0 + 16 * SAK * 4;
    // B x4: tile0 nb0 @k0 | tile1 nb0 @k0+4 | tile2 nb1 @k0 | tile3 nb1 @k0+4
    uint32_t bOff = ((n0 + 8 * (tt >> 1) + tr) * SAK + (tt & 1) * 4) * 4;

    unsigned long long acc[4][5];
    float accw[4] = {0.f, 0.f, 0.f, 0.f};
    #pragma unroll
    for (int i = 0; i < 4; i++)
        #pragma unroll
        for (int p = 0; p < 5; p++) acc[i][p] = 0ull;

    for (int ch = 0; ch < NCH; ch++) {
        if (ch + 1 < NCH) {
            issue_chunk(ch + 1, t, sbase, aSlice, Ad, M);
            cp_commit();
            cp_wait1();
        } else {
            cp_wait0();
        }
        __syncthreads();

        uint32_t bBase = sbase + SM_B + (ch & 1) * B_BUF + bOff;

        // frags: [mb(2)][nb(2)] of 4
        float c_[4][4];
        #pragma unroll
        for (int i = 0; i < 4; i++)
            #pragma unroll
            for (int j = 0; j < 4; j++) c_[i][j] = 0.f;

        #pragma unroll
        for (int ks = 0; ks < FD / 8; ks++) {
            uint32_t a0[4], a1[4], b[4];
            ldsm4(a0, aBase0 + ks * 32);
            ldsm4(a1, aBase1 + ks * 32);
            ldsm4(b, bBase + ks * 32);
            mma8(c_[0], a0, b);      mma8(c_[1], a0, b + 2);
            mma8(c_[2], a1, b);      mma8(c_[3], a1, b + 2);
        }

        // epilogue: w = exp2(CK - KK*dist), acc += w * M[n][:]
        const float2* Ms2 = (const float2*)(sm + SM_M + (ch & 1) * 2560);
        #pragma unroll
        for (int nb = 0; nb < 2; nb++) {
            #pragma unroll
            for (int c2 = 0; c2 < 2; c2++) {
                int nl = n0 + 8 * nb + 2 * tig + c2;
                float y2v = y2s[ch * BN + nl];
                unsigned long long m01, m23, m45, m67, m89;
                {
                    const float2* mr = Ms2 + nl * 5;
                    float2 v0 = mr[0], v1 = mr[1], v2 = mr[2], v3 = mr[3], v4 = mr[4];
                    asm("mov.b64 %0, {%1, %2};" : "=l"(m01) : "f"(v0.x), "f"(v0.y));
                    asm("mov.b64 %0, {%1, %2};" : "=l"(m23) : "f"(v1.x), "f"(v1.y));
                    asm("mov.b64 %0, {%1, %2};" : "=l"(m45) : "f"(v2.x), "f"(v2.y));
                    asm("mov.b64 %0, {%1, %2};" : "=l"(m67) : "f"(v3.x), "f"(v3.y));
                    asm("mov.b64 %0, {%1, %2};" : "=l"(m89) : "f"(v4.x), "f"(v4.y));
                }
                #pragma unroll
                for (int mb = 0; mb < 2; mb++) {
                    #pragma unroll
                    for (int h = 0; h < 2; h++) {
                        int ri = 2 * mb + h;
                        float d = c_[mb * 2 + nb][h * 2 + c2];
                        float q = fmaxf(fmaf(-2.f, d, x2r[ri] + y2v), 1e-12f);
                        float w = ex2f(fmaf(sqrt_ap(q), -KK, CK));
                        accw[ri] += w;
                        unsigned long long W = dup2(w);
                        fma2(acc[ri][0], W, m01);
                        fma2(acc[ri][1], W, m23);
                        fma2(acc[ri][2], W, m45);
                        fma2(acc[ri][3], W, m67);
                        fma2(acc[ri][4], W, m89);
                    }
                }
            }
        }
        __syncthreads();
    }

    // reduce across tig (4 lanes share rows, cover different n), write partials
    {
        #pragma unroll
        for (int ri = 0; ri < 4; ri++) {
            float v[11];
            #pragma unroll
            for (int p = 0; p < 5; p++) {
                float2 u = unpk(acc[ri][p]);
                v[2 * p] = u.x; v[2 * p + 1] = u.y;
            }
            v[10] = accw[ri];
            #pragma unroll
            for (int j = 0; j < 11; j++) {
                v[j] += __shfl_xor_sync(0xffffffffu, v[j], 1);
                v[j] += __shfl_xor_sync(0xffffffffu, v[j], 2);
            }
            if (tig == 0) {
                int mb = ri >> 1, h = ri & 1;
                int grow = rowBase + m0 + 16 * mb + 8 * h + g;
                float* out = g_part + ((size_t)(blockIdx.y * 4 + wn) * NROWS + grow) * 12;
                #pragma unroll
                for (int j = 0; j < 11; j++) out[j] = v[j];
            }
        }
    }
}

// ---------------- finalize ----------------
__global__ void finalize_kernel(float* __restrict__ out) {
    int idx = blockIdx.x * blockDim.x + threadIdx.x;
    if (idx >= NROWS * CDIM) return;
    int n = idx / CDIM;
    int c = idx - n * CDIM;
    float num = 0.f, den = 0.f;
    #pragma unroll
    for (int s = 0; s < SLICES * 4; s++) {
        const float* p = g_part + ((size_t)s * NROWS + n) * 12;
        num += p[c];
        den += p[10];
    }
    out[idx] = num / den;
}

extern "C" void kernel_launch(void* const* d_in, const int* in_sizes, int n_in,
                              void* d_out, int out_size) {
    const float* X  = (const float*)d_in[0];   // inputs  [4096, 160]
    const float* Ad = (const float*)d_in[1];   // Address [32768, 160]
    const float* M  = (const float*)d_in[2];   // M       [32768, 10]
    float* out = (float*)d_out;                // [4096, 10]

    cudaFuncSetAttribute(fused_mma_kernel,
                         cudaFuncAttributeMaxDynamicSharedMemorySize, SMEM_TOTAL);

    prep_y2_kernel<<<AADDR / 8, 256>>>(Ad);
    fused_mma_kernel<<<dim3(NROWS / BM, SLICES), THREADS, SMEM_TOTAL>>>(X, Ad, M);
    finalize_kernel<<<(NROWS * CDIM + 255) / 256, 256>>>(out);
}

// round 6
// speedup vs baseline: 1.7090x; 1.7090x over previous
#include <cuda_runtime.h>
#include <cuda_bf16.h>
#include <cstdint>

#define NROWS 4096
#define AADDR 32768
#define FD    160
#define CDIM  10

#define BM 128
#define BN 64
#define SLICES 16
#define APS (AADDR / SLICES)     // 2048
#define NCH (APS / BN)           // 32
#define THREADS 256

// bf16 row stride: 168 elements = 336 B. 336/4 = 84 banks, 84 mod 32 = 20 ->
// 8-row ldmatrix phases hit {0,20,8,28,16,4,24,12}+c: all 32 banks, conflict-free.
#define RSB 336
#define A_BYTES   (BM * RSB)              // 43008
#define B_BUF     (BN * RSB)              // 21504
#define SM_A   0
#define SM_B   (SM_A + A_BYTES)           // 43008
#define SM_M   (SM_B + 2 * B_BUF)         // 86016 (2 x 2560)
#define SM_Y2  (SM_M + 2 * 2560)          // 91136 (2048 f32)
#define SM_X2  (SM_Y2 + 8192)             // 99328 (128 f32)
#define SMEM_TOTAL (SM_X2 + 512)          // 99840  -> 2 CTAs/SM

#define KK 1.3115409462626940f   // log2(e)/1.1
#define CK 20.984655140203105f   // 16*log2(e)/1.1

__device__ float g_y2[AADDR];
__device__ __nv_bfloat16 g_adh[(size_t)AADDR * FD];   // bf16 copy of Address
__device__ float g_part[SLICES * 2 * NROWS * 12];

// ---------------- helpers ----------------
__device__ __forceinline__ uint32_t smem_u32(const void* p) {
    uint32_t a;
    asm("{ .reg .u64 t; cvta.to.shared.u64 t, %1; cvt.u32.u64 %0, t; }" : "=r"(a) : "l"(p));
    return a;
}
__device__ __forceinline__ float ex2f(float x) {
    float y; asm("ex2.approx.f32 %0, %1;" : "=f"(y) : "f"(x)); return y;
}
__device__ __forceinline__ float sqrt_ap(float x) {
    float y; asm("sqrt.approx.f32 %0, %1;" : "=f"(y) : "f"(x)); return y;
}
__device__ __forceinline__ unsigned long long dup2(float v) {
    unsigned long long r; asm("mov.b64 %0, {%1, %1};" : "=l"(r) : "f"(v)); return r;
}
__device__ __forceinline__ void fma2(unsigned long long& d, unsigned long long a, unsigned long long b) {
    asm("fma.rn.f32x2 %0, %1, %2, %0;" : "+l"(d) : "l"(a), "l"(b));
}
__device__ __forceinline__ float2 unpk(unsigned long long v) {
    float2 r; asm("mov.b64 {%0, %1}, %2;" : "=f"(r.x), "=f"(r.y) : "l"(v)); return r;
}
// pack two floats -> bf16x2 (lo = first arg). PTX: first src -> high half.
__device__ __forceinline__ uint32_t pack_bf(float lo, float hi) {
    uint32_t d;
    asm("cvt.rn.bf16x2.f32 %0, %1, %2;" : "=r"(d) : "f"(hi), "f"(lo));
    return d;
}
__device__ __forceinline__ void cp16(uint32_t dst, const void* src) {
    asm volatile("cp.async.cg.shared.global [%0], [%1], 16;" :: "r"(dst), "l"(src));
}
__device__ __forceinline__ void cp_commit() { asm volatile("cp.async.commit_group;" ::: "memory"); }
__device__ __forceinline__ void cp_wait1()  { asm volatile("cp.async.wait_group 1;" ::: "memory"); }
__device__ __forceinline__ void cp_wait0()  { asm volatile("cp.async.wait_group 0;" ::: "memory"); }

__device__ __forceinline__ void ldsm4(uint32_t* r, uint32_t addr) {
    asm volatile("ldmatrix.sync.aligned.m8n8.x4.shared.b16 {%0,%1,%2,%3}, [%4];"
                 : "=r"(r[0]), "=r"(r[1]), "=r"(r[2]), "=r"(r[3]) : "r"(addr));
}

// m16n8k16 bf16 MMA, fp32 accumulate
__device__ __forceinline__ void mma16(float* c, const uint32_t* a, const uint32_t* b) {
    asm volatile("mma.sync.aligned.m16n8k16.row.col.f32.bf16.bf16.f32 "
                 "{%0,%1,%2,%3}, {%4,%5,%6,%7}, {%8,%9}, {%0,%1,%2,%3};"
                 : "+f"(c[0]), "+f"(c[1]), "+f"(c[2]), "+f"(c[3])
                 : "r"(a[0]), "r"(a[1]), "r"(a[2]), "r"(a[3]),
                   "r"(b[0]), "r"(b[1]));
}

// ---------------- prep: y2 = ||Address||^2 (fp32) + bf16 copy of Address ----------------
__global__ void prep_kernel(const float* __restrict__ Ad) {
    int row = (blockIdx.x * 256 + threadIdx.x) >> 5;
    int lane = threadIdx.x & 31;
    const float4* p = (const float4*)(Ad + (size_t)row * FD);
    uint2* dst = (uint2*)(g_adh + (size_t)row * FD);
    float4 v = p[lane];
    uint2 w;
    w.x = pack_bf(v.x, v.y);
    w.y = pack_bf(v.z, v.w);
    dst[lane] = w;
    float s = v.x * v.x + v.y * v.y + v.z * v.z + v.w * v.w;
    if (lane < 8) {
        float4 u = p[32 + lane];
        uint2 w2;
        w2.x = pack_bf(u.x, u.y);
        w2.y = pack_bf(u.z, u.w);
        dst[32 + lane] = w2;
        s += u.x * u.x + u.y * u.y + u.z * u.z + u.w * u.w;
    }
    #pragma unroll
    for (int o = 16; o; o >>= 1) s += __shfl_xor_sync(0xffffffffu, s, o);
    if (lane == 0) g_y2[row] = s;
}

// ---------------- chunk loader (cp.async of bf16 B rows + fp32 M) ----------------
__device__ __forceinline__ void issue_chunk(int c, int t, uint32_t sbase, int aSlice,
                                            const float* __restrict__ M) {
    int buf = c & 1;
    int a0 = aSlice + c * BN;
    int r = t >> 2, q = t & 3;
    const char* src = (const char*)(g_adh + (size_t)(a0 + r) * FD);
    uint32_t bdst = sbase + SM_B + buf * B_BUF + r * RSB;
    #pragma unroll
    for (int i = 0; i < 5; i++) {
        int j = q + 4 * i;                        // 16B chunk index 0..19 (320 B/row)
        cp16(bdst + j * 16, src + j * 16);
    }
    if (t < (BN * CDIM) / 4)
        cp16(sbase + SM_M + buf * 2560 + t * 16,
             (const char*)(M + (size_t)a0 * CDIM) + t * 16);
}

// ---------------- main fused kernel ----------------
__global__ __launch_bounds__(THREADS, 2)
void fused_mma_kernel(const float* __restrict__ X,
                      const float* __restrict__ M) {
    extern __shared__ __align__(1024) char sm[];
    uint32_t sbase = smem_u32(sm);
    const float* y2s = (const float*)(sm + SM_Y2);

    int t = threadIdx.x;
    int wid = t >> 5, lane = t & 31;
    int g = lane >> 2, tig = lane & 3;
    int wm = wid & 3, wn = wid >> 2;     // 4 x 2 warp grid
    int m0 = wm * 32, n0 = wn * 32;
    int rowBase = blockIdx.x * BM;
    int aSlice = blockIdx.y * APS;

    // stage A tile as bf16: 128 rows x 160 el -> 320 B rows (stride 336)
    {
        int r = t >> 1, h = t & 1;
        const float4* src = (const float4*)(X + (size_t)(rowBase + r) * FD) + h * 20;
        uint32_t adst = sbase + SM_A + r * RSB + h * 160;
        #pragma unroll
        for (int i = 0; i < 20; i++) {
            float4 v = src[i];
            uint32_t lo = pack_bf(v.x, v.y);
            uint32_t hi = pack_bf(v.z, v.w);
            asm volatile("st.shared.v2.b32 [%0], {%1, %2};"
                         :: "r"(adst + i * 8), "r"(lo), "r"(hi));
        }
    }
    // stage y2 slice: 512 float4
    cp16(sbase + SM_Y2 + t * 16, (const char*)(g_y2 + aSlice) + t * 16);
    cp16(sbase + SM_Y2 + (t + 256) * 16, (const char*)(g_y2 + aSlice) + (t + 256) * 16);
    // x2 per row (exact fp32)
    if (t < BM) {
        const float4* p = (const float4*)(X + (size_t)(rowBase + t) * FD);
        float s = 0.f;
        #pragma unroll
        for (int i = 0; i < FD / 4; i++) {
            float4 v = p[i];
            s = fmaf(v.x, v.x, s); s = fmaf(v.y, v.y, s);
            s = fmaf(v.z, v.z, s); s = fmaf(v.w, v.w, s);
        }
        ((float*)(sm + SM_X2))[t] = s;
    }
    issue_chunk(0, t, sbase, aSlice, M);
    cp_commit();
    cp_wait0();
    __syncthreads();

    float x2r[4];
    #pragma unroll
    for (int i = 0; i < 4; i++) x2r[i] = ((const float*)(sm + SM_X2))[m0 + g + 8 * i];

    // ldmatrix per-lane addresses (b16 tiles: 8 rows x 16 B)
    int tr = lane & 7, tt = lane >> 3;
    // A x4: tile0 m+0 k+0 | tile1 m+8 k+0 | tile2 m+0 k+8 | tile3 m+8 k+8
    uint32_t aBase0 = sbase + SM_A + (m0 + (tt & 1) * 8 + tr) * RSB + (tt >> 1) * 16;
    uint32_t aBase1 = aBase0 + 16 * RSB;
    // B x4: tile0 n+0 k+0 | tile1 n+0 k+8 | tile2 n+8 k+0 | tile3 n+8 k+8
    uint32_t bOff0 = (n0 + (tt >> 1) * 8 + tr) * RSB + (tt & 1) * 16;
    uint32_t bOff1 = bOff0 + 16 * RSB;

    unsigned long long acc[4][5];
    float accw[4] = {0.f, 0.f, 0.f, 0.f};
    #pragma unroll
    for (int i = 0; i < 4; i++)
        #pragma unroll
        for (int p = 0; p < 5; p++) acc[i][p] = 0ull;

    for (int ch = 0; ch < NCH; ch++) {
        if (ch + 1 < NCH) {
            issue_chunk(ch + 1, t, sbase, aSlice, M);
            cp_commit();
            cp_wait1();
        } else {
            cp_wait0();
        }
        __syncthreads();

        uint32_t bBase = sbase + SM_B + (ch & 1) * B_BUF;

        float c_[8][4];
        #pragma unroll
        for (int i = 0; i < 8; i++)
            #pragma unroll
            for (int j = 0; j < 4; j++) c_[i][j] = 0.f;

        #pragma unroll
        for (int ks = 0; ks < FD / 16; ks++) {
            uint32_t a0[4], a1[4], b0[4], b1[4];
            ldsm4(a0, aBase0 + ks * 32);
            ldsm4(a1, aBase1 + ks * 32);
            ldsm4(b0, bBase + bOff0 + ks * 32);
            ldsm4(b1, bBase + bOff1 + ks * 32);
            mma16(c_[0], a0, b0);     mma16(c_[1], a0, b0 + 2);
            mma16(c_[2], a0, b1);     mma16(c_[3], a0, b1 + 2);
            mma16(c_[4], a1, b0);     mma16(c_[5], a1, b0 + 2);
            mma16(c_[6], a1, b1);     mma16(c_[7], a1, b1 + 2);
        }

        // epilogue: w = exp2(CK - KK*dist), acc += w * M[n][:]
        const float2* Ms2 = (const float2*)(sm + SM_M + (ch & 1) * 2560);
        #pragma unroll
        for (int nb = 0; nb < 4; nb++) {
            #pragma unroll
            for (int c2 = 0; c2 < 2; c2++) {
                int nl = n0 + 8 * nb + 2 * tig + c2;
                float y2v = y2s[ch * BN + nl];
                unsigned long long m01, m23, m45, m67, m89;
                {
                    const float2* mr = Ms2 + nl * 5;
                    float2 v0 = mr[0], v1 = mr[1], v2 = mr[2], v3 = mr[3], v4 = mr[4];
                    asm("mov.b64 %0, {%1, %2};" : "=l"(m01) : "f"(v0.x), "f"(v0.y));
                    asm("mov.b64 %0, {%1, %2};" : "=l"(m23) : "f"(v1.x), "f"(v1.y));
                    asm("mov.b64 %0, {%1, %2};" : "=l"(m45) : "f"(v2.x), "f"(v2.y));
                    asm("mov.b64 %0, {%1, %2};" : "=l"(m67) : "f"(v3.x), "f"(v3.y));
                    asm("mov.b64 %0, {%1, %2};" : "=l"(m89) : "f"(v4.x), "f"(v4.y));
                }
                #pragma unroll
                for (int mb = 0; mb < 2; mb++) {
                    #pragma unroll
                    for (int h = 0; h < 2; h++) {
                        int ri = 2 * mb + h;
                        float d = c_[mb * 4 + nb][h * 2 + c2];
                        float q = fmaxf(fmaf(-2.f, d, x2r[ri] + y2v), 1e-12f);
                        float w = ex2f(fmaf(sqrt_ap(q), -KK, CK));
                        accw[ri] += w;
                        unsigned long long W = dup2(w);
                        fma2(acc[ri][0], W, m01);
                        fma2(acc[ri][1], W, m23);
                        fma2(acc[ri][2], W, m45);
                        fma2(acc[ri][3], W, m67);
                        fma2(acc[ri][4], W, m89);
                    }
                }
            }
        }
        __syncthreads();
    }

    // reduce across tig, write partials
    {
        #pragma unroll
        for (int ri = 0; ri < 4; ri++) {
            float v[11];
            #pragma unroll
            for (int p = 0; p < 5; p++) {
                float2 u = unpk(acc[ri][p]);
                v[2 * p] = u.x; v[2 * p + 1] = u.y;
            }
            v[10] = accw[ri];
            #pragma unroll
            for (int j = 0; j < 11; j++) {
                v[j] += __shfl_xor_sync(0xffffffffu, v[j], 1);
                v[j] += __shfl_xor_sync(0xffffffffu, v[j], 2);
            }
            if (tig == 0) {
                int mb = ri >> 1, h = ri & 1;
                int grow = rowBase + m0 + 16 * mb + 8 * h + g;
                float* out = g_part + ((size_t)(blockIdx.y * 2 + wn) * NROWS + grow) * 12;
                #pragma unroll
                for (int j = 0; j < 11; j++) out[j] = v[j];
            }
        }
    }
}

// ---------------- finalize ----------------
__global__ void finalize_kernel(float* __restrict__ out) {
    int idx = blockIdx.x * blockDim.x + threadIdx.x;
    if (idx >= NROWS * CDIM) return;
    int n = idx / CDIM;
    int c = idx - n * CDIM;
    float num = 0.f, den = 0.f;
    #pragma unroll
    for (int s = 0; s < SLICES * 2; s++) {
        const float* p = g_part + ((size_t)s * NROWS + n) * 12;
        num += p[c];
        den += p[10];
    }
    out[idx] = num / den;
}

extern "C" void kernel_launch(void* const* d_in, const int* in_sizes, int n_in,
                              void* d_out, int out_size) {
    const float* X  = (const float*)d_in[0];   // inputs  [4096, 160]
    const float* Ad = (const float*)d_in[1];   // Address [32768, 160]
    const float* M  = (const float*)d_in[2];   // M       [32768, 10]
    float* out = (float*)d_out;                // [4096, 10]

    cudaFuncSetAttribute(fused_mma_kernel,
                         cudaFuncAttributeMaxDynamicSharedMemorySize, SMEM_TOTAL);

    prep_kernel<<<AADDR / 8, 256>>>(Ad);
    fused_mma_kernel<<<dim3(NROWS / BM, SLICES), THREADS, SMEM_TOTAL>>>(X, M);
    finalize_kernel<<<(NROWS * CDIM + 255) / 256, 256>>>(out);
}

// round 7
// speedup vs baseline: 1.7672x; 1.0341x over previous
#include <cuda_runtime.h>
#include <cstdint>

#define NROWS 4096
#define AADDR 32768
#define FD    160
#define CDIM  10

#define BM 128
#define BN 64
#define SLICES 16
#define APS (AADDR / SLICES)     // 2048
#define NCH (APS / BN)           // 32
#define THREADS 256

// fp8 row stride: 176 B = 44 banks == 12 mod 32 -> 8-row ldmatrix phases
// hit bank groups {0,12,24,4,16,28,8,20}x4 = all 32 banks, conflict-free.
#define RSB 176
#define A_BYTES   (BM * RSB)              // 22528
#define B_BUF     (BN * RSB)              // 11264
#define SM_A   0
#define SM_B   (SM_A + A_BYTES)           // 22528
#define SM_M   (SM_B + 2 * B_BUF)         // 45056 (2 x 2560)
#define SM_Y2  (SM_M + 2 * 2560)          // 50176 (2048 f32)
#define SM_X2  (SM_Y2 + 8192)             // 58368 (128 f32)
#define SMEM_TOTAL (SM_X2 + 512)          // 58880

#define KK 1.3115409462626940f   // log2(e)/1.1
#define CK 20.984655140203105f   // 16*log2(e)/1.1

__device__ float g_y2[AADDR];
__device__ uint8_t g_ad8[(size_t)AADDR * FD];   // e4m3 copy of Address
__device__ float g_part[SLICES * 2 * NROWS * 12];

// ---------------- helpers ----------------
__device__ __forceinline__ uint32_t smem_u32(const void* p) {
    uint32_t a;
    asm("{ .reg .u64 t; cvta.to.shared.u64 t, %1; cvt.u32.u64 %0, t; }" : "=r"(a) : "l"(p));
    return a;
}
__device__ __forceinline__ float ex2f(float x) {
    float y; asm("ex2.approx.f32 %0, %1;" : "=f"(y) : "f"(x)); return y;
}
__device__ __forceinline__ float sqrt_ap(float x) {
    float y; asm("sqrt.approx.f32 %0, %1;" : "=f"(y) : "f"(x)); return y;
}
__device__ __forceinline__ unsigned long long dup2(float v) {
    unsigned long long r; asm("mov.b64 %0, {%1, %1};" : "=l"(r) : "f"(v)); return r;
}
__device__ __forceinline__ void fma2(unsigned long long& d, unsigned long long a, unsigned long long b) {
    asm("fma.rn.f32x2 %0, %1, %2, %0;" : "+l"(d) : "l"(a), "l"(b));
}
__device__ __forceinline__ float2 unpk(unsigned long long v) {
    float2 r; asm("mov.b64 {%0, %1}, %2;" : "=f"(r.x), "=f"(r.y) : "l"(v)); return r;
}
// 4 floats -> 4 packed e4m3 bytes (x lowest byte)
__device__ __forceinline__ uint32_t pack_fp8x4(float4 v) {
    uint16_t lo, hi;
    asm("cvt.rn.satfinite.e4m3x2.f32 %0, %1, %2;" : "=h"(lo) : "f"(v.y), "f"(v.x));
    asm("cvt.rn.satfinite.e4m3x2.f32 %0, %1, %2;" : "=h"(hi) : "f"(v.w), "f"(v.z));
    return (uint32_t)lo | ((uint32_t)hi << 16);
}
__device__ __forceinline__ void cp16(uint32_t dst, const void* src) {
    asm volatile("cp.async.cg.shared.global [%0], [%1], 16;" :: "r"(dst), "l"(src));
}
__device__ __forceinline__ void cp_commit() { asm volatile("cp.async.commit_group;" ::: "memory"); }
__device__ __forceinline__ void cp_wait1()  { asm volatile("cp.async.wait_group 1;" ::: "memory"); }
__device__ __forceinline__ void cp_wait0()  { asm volatile("cp.async.wait_group 0;" ::: "memory"); }

__device__ __forceinline__ void ldsm4(uint32_t* r, uint32_t addr) {
    asm volatile("ldmatrix.sync.aligned.m8n8.x4.shared.b16 {%0,%1,%2,%3}, [%4];"
                 : "=r"(r[0]), "=r"(r[1]), "=r"(r[2]), "=r"(r[3]) : "r"(addr));
}

// m16n8k32 e4m3 MMA, fp32 accumulate (sm_89+)
__device__ __forceinline__ void mma32(float* c, const uint32_t* a, uint32_t b0, uint32_t b1) {
    asm volatile("mma.sync.aligned.m16n8k32.row.col.f32.e4m3.e4m3.f32 "
                 "{%0,%1,%2,%3}, {%4,%5,%6,%7}, {%8,%9}, {%0,%1,%2,%3};"
                 : "+f"(c[0]), "+f"(c[1]), "+f"(c[2]), "+f"(c[3])
                 : "r"(a[0]), "r"(a[1]), "r"(a[2]), "r"(a[3]),
                   "r"(b0), "r"(b1));
}

// ---------------- prep: y2 = ||Address||^2 (fp32) + e4m3 copy ----------------
__global__ void prep_kernel(const float* __restrict__ Ad) {
    int row = (blockIdx.x * 256 + threadIdx.x) >> 5;
    int lane = threadIdx.x & 31;
    const float4* p = (const float4*)(Ad + (size_t)row * FD);
    uint32_t* dst = (uint32_t*)(g_ad8 + (size_t)row * FD);
    float4 v = p[lane];
    dst[lane] = pack_fp8x4(v);
    float s = v.x * v.x + v.y * v.y + v.z * v.z + v.w * v.w;
    if (lane < 8) {
        float4 u = p[32 + lane];
        dst[32 + lane] = pack_fp8x4(u);
        s += u.x * u.x + u.y * u.y + u.z * u.z + u.w * u.w;
    }
    #pragma unroll
    for (int o = 16; o; o >>= 1) s += __shfl_xor_sync(0xffffffffu, s, o);
    if (lane == 0) g_y2[row] = s;
}

// ---------------- chunk loader: fp8 B rows + fp32 M ----------------
__device__ __forceinline__ void issue_chunk(int c, int t, uint32_t sbase, int aSlice,
                                            const float* __restrict__ M) {
    int buf = c & 1;
    int a0 = aSlice + c * BN;
    int r = t >> 2, q = t & 3;
    const char* src = (const char*)(g_ad8 + (size_t)(a0 + r) * FD);
    uint32_t bdst = sbase + SM_B + buf * B_BUF + r * RSB;
    #pragma unroll
    for (int j = q; j < 10; j += 4)               // 10 x 16B per row (160 B)
        cp16(bdst + j * 16, src + j * 16);
    if (t < (BN * CDIM) / 4)
        cp16(sbase + SM_M + buf * 2560 + t * 16,
             (const char*)(M + (size_t)a0 * CDIM) + t * 16);
}

// ---------------- main fused kernel ----------------
__global__ __launch_bounds__(THREADS, 2)
void fused_mma_kernel(const float* __restrict__ X,
                      const float* __restrict__ M) {
    extern __shared__ __align__(1024) char sm[];
    uint32_t sbase = smem_u32(sm);
    const float* y2s = (const float*)(sm + SM_Y2);

    int t = threadIdx.x;
    int wid = t >> 5, lane = t & 31;
    int g = lane >> 2, tig = lane & 3;
    int wm = wid & 3, wn = wid >> 2;     // 4 x 2 warp grid
    int m0 = wm * 32, n0 = wn * 32;
    int rowBase = blockIdx.x * BM;
    int aSlice = blockIdx.y * APS;

    // stage A tile as e4m3: 128 rows x 160 B (stride 176)
    {
        int r = t >> 1, h = t & 1;
        const float4* src = (const float4*)(X + (size_t)(rowBase + r) * FD) + h * 20;
        uint32_t adst = sbase + SM_A + r * RSB + h * 80;
        #pragma unroll
        for (int i = 0; i < 20; i++) {
            uint32_t w = pack_fp8x4(src[i]);
            asm volatile("st.shared.b32 [%0], %1;" :: "r"(adst + i * 4), "r"(w));
        }
    }
    // stage y2 slice: 512 float4
    cp16(sbase + SM_Y2 + t * 16, (const char*)(g_y2 + aSlice) + t * 16);
    cp16(sbase + SM_Y2 + (t + 256) * 16, (const char*)(g_y2 + aSlice) + (t + 256) * 16);
    // x2 per row (exact fp32)
    if (t < BM) {
        const float4* p = (const float4*)(X + (size_t)(rowBase + t) * FD);
        float s = 0.f;
        #pragma unroll
        for (int i = 0; i < FD / 4; i++) {
            float4 v = p[i];
            s = fmaf(v.x, v.x, s); s = fmaf(v.y, v.y, s);
            s = fmaf(v.z, v.z, s); s = fmaf(v.w, v.w, s);
        }
        ((float*)(sm + SM_X2))[t] = s;
    }
    issue_chunk(0, t, sbase, aSlice, M);
    cp_commit();
    cp_wait0();
    __syncthreads();

    float x2r[4];
    #pragma unroll
    for (int i = 0; i < 4; i++) x2r[i] = ((const float*)(sm + SM_X2))[m0 + g + 8 * i];

    // ldmatrix per-lane addresses (tiles: 8 rows x 16 B = 8r x 16 fp8)
    int tr = lane & 7, tt = lane >> 3;
    // x4 tiles: (r+0,klo) (r+8,klo) (r+0,khi) (r+8,khi); khi = +16 B
    uint32_t aBase0 = sbase + SM_A + (m0 + (tt & 1) * 8 + tr) * RSB + (tt >> 1) * 16;
    uint32_t aBase1 = aBase0 + 16 * RSB;
    uint32_t bOff0 = (n0 + (tt & 1) * 8 + tr) * RSB + (tt >> 1) * 16;
    uint32_t bOff1 = bOff0 + 16 * RSB;

    unsigned long long acc[4][5];
    float accw[4] = {0.f, 0.f, 0.f, 0.f};
    #pragma unroll
    for (int i = 0; i < 4; i++)
        #pragma unroll
        for (int p = 0; p < 5; p++) acc[i][p] = 0ull;

    for (int ch = 0; ch < NCH; ch++) {
        if (ch + 1 < NCH) {
            issue_chunk(ch + 1, t, sbase, aSlice, M);
            cp_commit();
            cp_wait1();
        } else {
            cp_wait0();
        }
        __syncthreads();

        uint32_t bBase = sbase + SM_B + (ch & 1) * B_BUF;

        // frags c_[mb*4+nb]: mb in {0,1} (m+0..15, m+16..31), nb in 0..3 (n+8*nb)
        float c_[8][4];
        #pragma unroll
        for (int i = 0; i < 8; i++)
            #pragma unroll
            for (int j = 0; j < 4; j++) c_[i][j] = 0.f;

        #pragma unroll
        for (int ks = 0; ks < FD / 32; ks++) {
            uint32_t a0[4], a1[4], b0[4], b1[4];
            ldsm4(a0, aBase0 + ks * 32);
            ldsm4(a1, aBase1 + ks * 32);
            ldsm4(b0, bBase + bOff0 + ks * 32);   // r0=nb0 klo, r1=nb1 klo, r2=nb0 khi, r3=nb1 khi
            ldsm4(b1, bBase + bOff1 + ks * 32);   // nb2 / nb3
            mma32(c_[0], a0, b0[0], b0[2]);   mma32(c_[1], a0, b0[1], b0[3]);
            mma32(c_[2], a0, b1[0], b1[2]);   mma32(c_[3], a0, b1[1], b1[3]);
            mma32(c_[4], a1, b0[0], b0[2]);   mma32(c_[5], a1, b0[1], b0[3]);
            mma32(c_[6], a1, b1[0], b1[2]);   mma32(c_[7], a1, b1[1], b1[3]);
        }

        // epilogue: w = exp2(CK - KK*dist), acc += w * M[n][:]
        const float2* Ms2 = (const float2*)(sm + SM_M + (ch & 1) * 2560);
        #pragma unroll
        for (int nb = 0; nb < 4; nb++) {
            #pragma unroll
            for (int c2 = 0; c2 < 2; c2++) {
                int nl = n0 + 8 * nb + 2 * tig + c2;
                float y2v = y2s[ch * BN + nl];
                unsigned long long m01, m23, m45, m67, m89;
                {
                    const float2* mr = Ms2 + nl * 5;
                    float2 v0 = mr[0], v1 = mr[1], v2 = mr[2], v3 = mr[3], v4 = mr[4];
                    asm("mov.b64 %0, {%1, %2};" : "=l"(m01) : "f"(v0.x), "f"(v0.y));
                    asm("mov.b64 %0, {%1, %2};" : "=l"(m23) : "f"(v1.x), "f"(v1.y));
                    asm("mov.b64 %0, {%1, %2};" : "=l"(m45) : "f"(v2.x), "f"(v2.y));
                    asm("mov.b64 %0, {%1, %2};" : "=l"(m67) : "f"(v3.x), "f"(v3.y));
                    asm("mov.b64 %0, {%1, %2};" : "=l"(m89) : "f"(v4.x), "f"(v4.y));
                }
                #pragma unroll
                for (int mb = 0; mb < 2; mb++) {
                    #pragma unroll
                    for (int h = 0; h < 2; h++) {
                        int ri = 2 * mb + h;
                        float d = c_[mb * 4 + nb][h * 2 + c2];
                        float q = fmaxf(fmaf(-2.f, d, x2r[ri] + y2v), 1e-12f);
                        float w = ex2f(fmaf(sqrt_ap(q), -KK, CK));
                        accw[ri] += w;
                        unsigned long long W = dup2(w);
                        fma2(acc[ri][0], W, m01);
                        fma2(acc[ri][1], W, m23);
                        fma2(acc[ri][2], W, m45);
                        fma2(acc[ri][3], W, m67);
                        fma2(acc[ri][4], W, m89);
                    }
                }
            }
        }
        __syncthreads();
    }

    // reduce across tig, write partials
    {
        #pragma unroll
        for (int ri = 0; ri < 4; ri++) {
            float v[11];
            #pragma unroll
            for (int p = 0; p < 5; p++) {
                float2 u = unpk(acc[ri][p]);
                v[2 * p] = u.x; v[2 * p + 1] = u.y;
            }
            v[10] = accw[ri];
            #pragma unroll
            for (int j = 0; j < 11; j++) {
                v[j] += __shfl_xor_sync(0xffffffffu, v[j], 1);
                v[j] += __shfl_xor_sync(0xffffffffu, v[j], 2);
            }
            if (tig == 0) {
                int mb = ri >> 1, h = ri & 1;
                int grow = rowBase + m0 + 16 * mb + 8 * h + g;
                float* out = g_part + ((size_t)(blockIdx.y * 2 + wn) * NROWS + grow) * 12;
                #pragma unroll
                for (int j = 0; j < 11; j++) out[j] = v[j];
            }
        }
    }
}

// ---------------- finalize ----------------
__global__ void finalize_kernel(float* __restrict__ out) {
    int idx = blockIdx.x * blockDim.x + threadIdx.x;
    if (idx >= NROWS * CDIM) return;
    int n = idx / CDIM;
    int c = idx - n * CDIM;
    float num = 0.f, den = 0.f;
    #pragma unroll
    for (int s = 0; s < SLICES * 2; s++) {
        const float* p = g_part + ((size_t)s * NROWS + n) * 12;
        num += p[c];
        den += p[10];
    }
    out[idx] = num / den;
}

extern "C" void kernel_launch(void* const* d_in, const int* in_sizes, int n_in,
                              void* d_out, int out_size) {
    const float* X  = (const float*)d_in[0];   // inputs  [4096, 160]
    const float* Ad = (const float*)d_in[1];   // Address [32768, 160]
    const float* M  = (const float*)d_in[2];   // M       [32768, 10]
    float* out = (float*)d_out;                // [4096, 10]

    cudaFuncSetAttribute(fused_mma_kernel,
                         cudaFuncAttributeMaxDynamicSharedMemorySize, SMEM_TOTAL);

    prep_kernel<<<AADDR / 8, 256>>>(Ad);
    fused_mma_kernel<<<dim3(NROWS / BM, SLICES), THREADS, SMEM_TOTAL>>>(X, M);
    finalize_kernel<<<(NROWS * CDIM + 255) / 256, 256>>>(out);
}

// round 8
// speedup vs baseline: 2.0876x; 1.1813x over previous
#include <cuda_runtime.h>
#include <cuda_bf16.h>
#include <cstdint>

#define NROWS 4096
#define AADDR 32768
#define FD    160
#define CDIM  10

#define BM 128
#define BN 64
#define SLICES 32
#define APS (AADDR / SLICES)     // 1024
#define NCH (APS / BN)           // 16
#define THREADS 256

// fp8 row stride: 176 B == 44 banks == 12 mod 32 -> ldmatrix phases conflict-free
#define RSB 176
#define A_BYTES (BM * RSB)                // 22528
#define B_BUF   (BN * RSB)                // 11264
#define MT_BUF  2048                      // 16 x 64 bf16
#define SM_A   0
#define SM_B   (SM_A + A_BYTES)           // 22528
#define SM_MT  (SM_B + 2 * B_BUF)         // 45056
#define SM_Y2  (SM_MT + 2 * MT_BUF)       // 49152 (1024 f32)
#define SM_X2  (SM_Y2 + 4096)             // 53248 (128 f32)
#define SMEM_TOTAL (SM_X2 + 512)          // 53760

#define KK 1.3115409462626940f   // log2(e)/1.1
#define CK 20.984655140203105f   // 16*log2(e)/1.1

__device__ float g_y2[AADDR];
__device__ uint8_t g_ad8[(size_t)AADDR * FD];            // e4m3 Address
__device__ __nv_bfloat16 g_mt[(AADDR / 64) * 16 * 64];   // M transposed + ones row, bf16
__device__ float g_part[SLICES * 2 * NROWS * 12];

// ---------------- helpers ----------------
__device__ __forceinline__ uint32_t smem_u32(const void* p) {
    uint32_t a;
    asm("{ .reg .u64 t; cvta.to.shared.u64 t, %1; cvt.u32.u64 %0, t; }" : "=r"(a) : "l"(p));
    return a;
}
__device__ __forceinline__ float ex2f(float x) {
    float y; asm("ex2.approx.f32 %0, %1;" : "=f"(y) : "f"(x)); return y;
}
__device__ __forceinline__ float sqrt_ap(float x) {
    float y; asm("sqrt.approx.f32 %0, %1;" : "=f"(y) : "f"(x)); return y;
}
// pack two floats -> bf16x2 (first arg = low half)
__device__ __forceinline__ uint32_t pack_bf(float lo, float hi) {
    uint32_t d;
    asm("cvt.rn.bf16x2.f32 %0, %1, %2;" : "=r"(d) : "f"(hi), "f"(lo));
    return d;
}
// 4 floats -> 4 packed e4m3 bytes
__device__ __forceinline__ uint32_t pack_fp8x4(float4 v) {
    uint16_t lo, hi;
    asm("cvt.rn.satfinite.e4m3x2.f32 %0, %1, %2;" : "=h"(lo) : "f"(v.y), "f"(v.x));
    asm("cvt.rn.satfinite.e4m3x2.f32 %0, %1, %2;" : "=h"(hi) : "f"(v.w), "f"(v.z));
    return (uint32_t)lo | ((uint32_t)hi << 16);
}
__device__ __forceinline__ void cp16(uint32_t dst, const void* src) {
    asm volatile("cp.async.cg.shared.global [%0], [%1], 16;" :: "r"(dst), "l"(src));
}
__device__ __forceinline__ void cp_commit() { asm volatile("cp.async.commit_group;" ::: "memory"); }
__device__ __forceinline__ void cp_wait1()  { asm volatile("cp.async.wait_group 1;" ::: "memory"); }
__device__ __forceinline__ void cp_wait0()  { asm volatile("cp.async.wait_group 0;" ::: "memory"); }

__device__ __forceinline__ void ldsm4(uint32_t* r, uint32_t addr) {
    asm volatile("ldmatrix.sync.aligned.m8n8.x4.shared.b16 {%0,%1,%2,%3}, [%4];"
                 : "=r"(r[0]), "=r"(r[1]), "=r"(r[2]), "=r"(r[3]) : "r"(addr));
}

// m16n8k32 e4m3 MMA, fp32 accumulate
__device__ __forceinline__ void mma32(float* c, const uint32_t* a, uint32_t b0, uint32_t b1) {
    asm volatile("mma.sync.aligned.m16n8k32.row.col.f32.e4m3.e4m3.f32 "
                 "{%0,%1,%2,%3}, {%4,%5,%6,%7}, {%8,%9}, {%0,%1,%2,%3};"
                 : "+f"(c[0]), "+f"(c[1]), "+f"(c[2]), "+f"(c[3])
                 : "r"(a[0]), "r"(a[1]), "r"(a[2]), "r"(a[3]), "r"(b0), "r"(b1));
}
// m16n8k16 bf16 MMA, fp32 accumulate (P @ M_T)
__device__ __forceinline__ void mma16b(float* c, const uint32_t* a, uint32_t b0, uint32_t b1) {
    asm volatile("mma.sync.aligned.m16n8k16.row.col.f32.bf16.bf16.f32 "
                 "{%0,%1,%2,%3}, {%4,%5,%6,%7}, {%8,%9}, {%0,%1,%2,%3};"
                 : "+f"(c[0]), "+f"(c[1]), "+f"(c[2]), "+f"(c[3])
                 : "r"(a[0]), "r"(a[1]), "r"(a[2]), "r"(a[3]), "r"(b0), "r"(b1));
}

// ---------------- prep: y2, e4m3 Address copy, bf16 M^T blocks ----------------
__global__ void prep_kernel(const float* __restrict__ Ad, const float* __restrict__ M) {
    int row = (blockIdx.x * 256 + threadIdx.x) >> 5;
    int lane = threadIdx.x & 31;
    const float4* p = (const float4*)(Ad + (size_t)row * FD);
    uint32_t* dst = (uint32_t*)(g_ad8 + (size_t)row * FD);
    float4 v = p[lane];
    dst[lane] = pack_fp8x4(v);
    float s = v.x * v.x + v.y * v.y + v.z * v.z + v.w * v.w;
    if (lane < 8) {
        float4 u = p[32 + lane];
        dst[32 + lane] = pack_fp8x4(u);
        s += u.x * u.x + u.y * u.y + u.z * u.z + u.w * u.w;
    }
    // M^T block: g_mt[blk][c][a&63], c=10 -> 1.0 (sum_w), c>10 -> 0
    if (lane < 16) {
        float mv = 0.f;
        if (lane < CDIM) mv = M[(size_t)row * CDIM + lane];
        else if (lane == CDIM) mv = 1.0f;
        g_mt[((size_t)(row >> 6) * 16 + lane) * 64 + (row & 63)] = __float2bfloat16(mv);
    }
    #pragma unroll
    for (int o = 16; o; o >>= 1) s += __shfl_xor_sync(0xffffffffu, s, o);
    if (lane == 0) g_y2[row] = s;
}

// ---------------- chunk loader: fp8 B rows + bf16 M^T block ----------------
__device__ __forceinline__ void issue_chunk(int c, int t, uint32_t sbase, int blkBase) {
    int buf = c & 1;
    int aBlk = blkBase + c;                       // global 64-address block index
    int r = t >> 2, q = t & 3;
    const char* src = (const char*)(g_ad8 + (size_t)(aBlk * 64 + r) * FD);
    uint32_t bdst = sbase + SM_B + buf * B_BUF + r * RSB;
    #pragma unroll
    for (int j = q; j < 10; j += 4)               // 10 x 16B per row
        cp16(bdst + j * 16, src + j * 16);
    if (t < MT_BUF / 16)                          // 2 KB M^T block
        cp16(sbase + SM_MT + buf * MT_BUF + t * 16,
             (const char*)(g_mt + (size_t)aBlk * 16 * 64) + t * 16);
}

// ---------------- main fused kernel ----------------
__global__ __launch_bounds__(THREADS, 2)
void fused_mma_kernel(const float* __restrict__ X) {
    extern __shared__ __align__(1024) char sm[];
    uint32_t sbase = smem_u32(sm);
    const float* y2s = (const float*)(sm + SM_Y2);

    int t = threadIdx.x;
    int wid = t >> 5, lane = t & 31;
    int g = lane >> 2, tig = lane & 3;
    int wm = wid & 3, wn = wid >> 2;     // 4 x 2 warp grid
    int m0 = wm * 32, n0 = wn * 32;
    int rowBase = blockIdx.x * BM;
    int aSlice = blockIdx.y * APS;
    int blkBase = blockIdx.y * NCH;

    // stage A tile as e4m3
    {
        int r = t >> 1, h = t & 1;
        const float4* src = (const float4*)(X + (size_t)(rowBase + r) * FD) + h * 20;
        uint32_t adst = sbase + SM_A + r * RSB + h * 80;
        #pragma unroll
        for (int i = 0; i < 20; i++) {
            uint32_t w = pack_fp8x4(src[i]);
            asm volatile("st.shared.b32 [%0], %1;" :: "r"(adst + i * 4), "r"(w));
        }
    }
    // stage y2 slice: 1024 floats = 256 x 16B
    cp16(sbase + SM_Y2 + t * 16, (const char*)(g_y2 + aSlice) + t * 16);
    // x2 per row (exact fp32)
    if (t < BM) {
        const float4* p = (const float4*)(X + (size_t)(rowBase + t) * FD);
        float s = 0.f;
        #pragma unroll
        for (int i = 0; i < FD / 4; i++) {
            float4 v = p[i];
            s = fmaf(v.x, v.x, s); s = fmaf(v.y, v.y, s);
            s = fmaf(v.z, v.z, s); s = fmaf(v.w, v.w, s);
        }
        ((float*)(sm + SM_X2))[t] = s;
    }
    issue_chunk(0, t, sbase, blkBase);
    cp_commit();
    cp_wait0();
    __syncthreads();

    float x2r[4];
    #pragma unroll
    for (int i = 0; i < 4; i++) x2r[i] = ((const float*)(sm + SM_X2))[m0 + g + 8 * i];

    // QK ldmatrix per-lane addresses (tiles: 8 rows x 16 B)
    int tr = lane & 7, tt = lane >> 3;
    uint32_t aBase0 = sbase + SM_A + (m0 + (tt & 1) * 8 + tr) * RSB + (tt >> 1) * 16;
    uint32_t aBase1 = aBase0 + 16 * RSB;
    uint32_t bOff0 = (n0 + (tt & 1) * 8 + tr) * RSB + (tt >> 1) * 16;
    uint32_t bOff1 = bOff0 + 16 * RSB;
    // M^T ldmatrix: tiles (c0-7,klo)(c8-15,klo)(c0-7,khi)(c8-15,khi)
    uint32_t mtOff = ((tt & 1) * 8 + tr) * 128 + (n0 + (tt >> 1) * 8) * 2;

    // persistent output accumulators: d_[mb][no][4]
    float d_[2][2][4];
    #pragma unroll
    for (int i = 0; i < 2; i++)
        #pragma unroll
        for (int j = 0; j < 2; j++)
            #pragma unroll
            for (int k = 0; k < 4; k++) d_[i][j][k] = 0.f;

    for (int ch = 0; ch < NCH; ch++) {
        if (ch + 1 < NCH) {
            issue_chunk(ch + 1, t, sbase, blkBase);
            cp_commit();
            cp_wait1();
        } else {
            cp_wait0();
        }
        __syncthreads();

        uint32_t bBase = sbase + SM_B + (ch & 1) * B_BUF;

        float c_[8][4];
        #pragma unroll
        for (int i = 0; i < 8; i++)
            #pragma unroll
            for (int j = 0; j < 4; j++) c_[i][j] = 0.f;

        #pragma unroll
        for (int ks = 0; ks < FD / 32; ks++) {
            uint32_t a0[4], a1[4], b0[4], b1[4];
            ldsm4(a0, aBase0 + ks * 32);
            ldsm4(a1, aBase1 + ks * 32);
            ldsm4(b0, bBase + bOff0 + ks * 32);
            ldsm4(b1, bBase + bOff1 + ks * 32);
            mma32(c_[0], a0, b0[0], b0[2]);   mma32(c_[1], a0, b0[1], b0[3]);
            mma32(c_[2], a0, b1[0], b1[2]);   mma32(c_[3], a0, b1[1], b1[3]);
            mma32(c_[4], a1, b0[0], b0[2]);   mma32(c_[5], a1, b0[1], b0[3]);
            mma32(c_[6], a1, b1[0], b1[2]);   mma32(c_[7], a1, b1[1], b1[3]);
        }

        // ---- weights in C-frag layout -> bf16 A-frags of P@M_T ----
        uint32_t aP[2][2][4];    // [mb][kstep16][4]
        #pragma unroll
        for (int mb = 0; mb < 2; mb++) {
            #pragma unroll
            for (int nb = 0; nb < 4; nb++) {
                float w[4];
                #pragma unroll
                for (int h = 0; h < 2; h++) {
                    #pragma unroll
                    for (int c2 = 0; c2 < 2; c2++) {
                        int nl = n0 + 8 * nb + 2 * tig + c2;
                        float d = c_[mb * 4 + nb][h * 2 + c2];
                        float q = fmaxf(fmaf(-2.f, d, x2r[2 * mb + h] + y2s[ch * BN + nl]), 1e-12f);
                        w[h * 2 + c2] = ex2f(fmaf(sqrt_ap(q), -KK, CK));
                    }
                }
                int ks = nb >> 1, kh = nb & 1;
                aP[mb][ks][kh * 2 + 0] = pack_bf(w[0], w[1]);   // row g
                aP[mb][ks][kh * 2 + 1] = pack_bf(w[2], w[3]);   // row g+8
            }
        }

        // ---- M^T B-frags + P@M_T accumulation ----
        {
            uint32_t mtb = sbase + SM_MT + (ch & 1) * MT_BUF + mtOff;
            uint32_t bm0[4], bm1[4];
            ldsm4(bm0, mtb);          // k = n0+0..15
            ldsm4(bm1, mtb + 32);     // k = n0+16..31
            #pragma unroll
            for (int mb = 0; mb < 2; mb++) {
                mma16b(d_[mb][0], aP[mb][0], bm0[0], bm0[2]);
                mma16b(d_[mb][1], aP[mb][0], bm0[1], bm0[3]);
                mma16b(d_[mb][0], aP[mb][1], bm1[0], bm1[2]);
                mma16b(d_[mb][1], aP[mb][1], bm1[1], bm1[3]);
            }
        }
        __syncthreads();
    }

    // write partials: thread owns (row g/g+8 +16mb, c = 8no+2tig+c2)
    {
        float* base = g_part + (size_t)(blockIdx.y * 2 + wn) * NROWS * 12;
        #pragma unroll
        for (int mb = 0; mb < 2; mb++) {
            #pragma unroll
            for (int no = 0; no < 2; no++) {
                #pragma unroll
                for (int h = 0; h < 2; h++) {
                    #pragma unroll
                    for (int c2 = 0; c2 < 2; c2++) {
                        int c = 8 * no + 2 * tig + c2;
                        if (c <= 10) {
                            int grow = rowBase + m0 + 16 * mb + 8 * h + g;
                            base[(size_t)grow * 12 + c] = d_[mb][no][2 * h + c2];
                        }
                    }
                }
            }
        }
    }
}

// ---------------- finalize ----------------
__global__ void finalize_kernel(float* __restrict__ out) {
    int idx = blockIdx.x * blockDim.x + threadIdx.x;
    if (idx >= NROWS * CDIM) return;
    int n = idx / CDIM;
    int c = idx - n * CDIM;
    float num = 0.f, den = 0.f;
    #pragma unroll
    for (int s = 0; s < SLICES * 2; s++) {
        const float* p = g_part + ((size_t)s * NROWS + n) * 12;
        num += p[c];
        den += p[10];
    }
    out[idx] = num / den;
}

extern "C" void kernel_launch(void* const* d_in, const int* in_sizes, int n_in,
                              void* d_out, int out_size) {
    const float* X  = (const float*)d_in[0];   // inputs  [4096, 160]
    const float* Ad = (const float*)d_in[1];   // Address [32768, 160]
    const float* M  = (const float*)d_in[2];   // M       [32768, 10]
    float* out = (float*)d_out;                // [4096, 10]

    cudaFuncSetAttribute(fused_mma_kernel,
                         cudaFuncAttributeMaxDynamicSharedMemorySize, SMEM_TOTAL);

    prep_kernel<<<AADDR / 8, 256>>>(Ad, M);
    fused_mma_kernel<<<dim3(NROWS / BM, SLICES), THREADS, SMEM_TOTAL>>>(X);
    finalize_kernel<<<(NROWS * CDIM + 255) / 256, 256>>>(out);
}

// round 11
// speedup vs baseline: 2.2247x; 1.0657x over previous
#include <cuda_runtime.h>
#include <cuda_fp16.h>
#include <cstdint>

#define NROWS 4096
#define AADDR 32768
#define FD    160
#define CDIM  10

#define BM 128
#define BN 64
#define SLICES 32
#define APS (AADDR / SLICES)     // 1024
#define NCH (APS / BN)           // 16
#define THREADS 256

// fp8 row stride: 176 B == 44 banks == 12 mod 32 -> ldmatrix phases conflict-free
#define RSB 176
#define A_BYTES (BM * RSB)                // 22528
#define B_BUF   (BN * RSB)                // 11264
#define MT_BUF  2048                      // 16 x 64 fp16
#define SM_A   0
#define SM_B   (SM_A + A_BYTES)           // 22528
#define SM_MT  (SM_B + 3 * B_BUF)         // 56320
#define SM_Y2  (SM_MT + 3 * MT_BUF)       // 62464 (1024 f32)
#define SM_X2  (SM_Y2 + 4096)             // 66560 (128 f32)
#define SMEM_TOTAL (SM_X2 + 512)          // 67072  (2 CTAs/SM)

#define KK 1.3115409462626940f    // log2(e)/1.1
#define CK12 15.738491355152328f  // 12*log2(e)/1.1  (shift C=12: fp16-safe weights)

__device__ float g_y2[AADDR];
__device__ uint8_t g_ad8[(size_t)AADDR * FD];      // e4m3 Address
__device__ __half g_mt[(AADDR / 64) * 16 * 64];    // M^T blocks (+ones row), fp16
__device__ float g_part[SLICES * 2 * NROWS * 12];

// ---------------- helpers ----------------
__device__ __forceinline__ uint32_t smem_u32(const void* p) {
    uint32_t a;
    asm("{ .reg .u64 t; cvta.to.shared.u64 t, %1; cvt.u32.u64 %0, t; }" : "=r"(a) : "l"(p));
    return a;
}
__device__ __forceinline__ float sqrt_ap(float x) {
    float y; asm("sqrt.approx.f32 %0, %1;" : "=f"(y) : "f"(x)); return y;
}
// pack two f32 -> f16x2 (first arg = low half)
__device__ __forceinline__ uint32_t pack_h2(float lo, float hi) {
    uint32_t d;
    asm("cvt.rn.f16x2.f32 %0, %1, %2;" : "=r"(d) : "f"(hi), "f"(lo));
    return d;
}
__device__ __forceinline__ uint32_t ex2_h2(uint32_t a) {
    uint32_t d;
    asm("ex2.approx.f16x2 %0, %1;" : "=r"(d) : "r"(a));
    return d;
}
// 4 floats -> 4 packed e4m3 bytes
__device__ __forceinline__ uint32_t pack_fp8x4(float4 v) {
    uint16_t lo, hi;
    asm("cvt.rn.satfinite.e4m3x2.f32 %0, %1, %2;" : "=h"(lo) : "f"(v.y), "f"(v.x));
    asm("cvt.rn.satfinite.e4m3x2.f32 %0, %1, %2;" : "=h"(hi) : "f"(v.w), "f"(v.z));
    return (uint32_t)lo | ((uint32_t)hi << 16);
}
__device__ __forceinline__ void cp16(uint32_t dst, const void* src) {
    asm volatile("cp.async.cg.shared.global [%0], [%1], 16;" :: "r"(dst), "l"(src));
}
__device__ __forceinline__ void cp_commit() { asm volatile("cp.async.commit_group;" ::: "memory"); }
__device__ __forceinline__ void cp_wait1()  { asm volatile("cp.async.wait_group 1;" ::: "memory"); }
__device__ __forceinline__ void cp_wait0()  { asm volatile("cp.async.wait_group 0;" ::: "memory"); }

__device__ __forceinline__ void ldsm4(uint32_t* r, uint32_t addr) {
    asm volatile("ldmatrix.sync.aligned.m8n8.x4.shared.b16 {%0,%1,%2,%3}, [%4];"
                 : "=r"(r[0]), "=r"(r[1]), "=r"(r[2]), "=r"(r[3]) : "r"(addr));
}

// m16n8k32 e4m3 MMA, fp32 accumulate
__device__ __forceinline__ void mma32(float* c, const uint32_t* a, uint32_t b0, uint32_t b1) {
    asm volatile("mma.sync.aligned.m16n8k32.row.col.f32.e4m3.e4m3.f32 "
                 "{%0,%1,%2,%3}, {%4,%5,%6,%7}, {%8,%9}, {%0,%1,%2,%3};"
                 : "+f"(c[0]), "+f"(c[1]), "+f"(c[2]), "+f"(c[3])
                 : "r"(a[0]), "r"(a[1]), "r"(a[2]), "r"(a[3]), "r"(b0), "r"(b1));
}
// m16n8k16 fp16 MMA, fp32 accumulate (P @ M_T)
__device__ __forceinline__ void mma16h(float* c, const uint32_t* a, uint32_t b0, uint32_t b1) {
    asm volatile("mma.sync.aligned.m16n8k16.row.col.f32.f16.f16.f32 "
                 "{%0,%1,%2,%3}, {%4,%5,%6,%7}, {%8,%9}, {%0,%1,%2,%3};"
                 : "+f"(c[0]), "+f"(c[1]), "+f"(c[2]), "+f"(c[3])
                 : "r"(a[0]), "r"(a[1]), "r"(a[2]), "r"(a[3]), "r"(b0), "r"(b1));
}

// ---------------- prep 1: y2 + e4m3 Address copy ----------------
__global__ void prep_kernel(const float* __restrict__ Ad) {
    int row = (blockIdx.x * 256 + threadIdx.x) >> 5;
    int lane = threadIdx.x & 31;
    const float4* p = (const float4*)(Ad + (size_t)row * FD);
    uint32_t* dst = (uint32_t*)(g_ad8 + (size_t)row * FD);
    float4 v = p[lane];
    dst[lane] = pack_fp8x4(v);
    float s = v.x * v.x + v.y * v.y + v.z * v.z + v.w * v.w;
    if (lane < 8) {
        float4 u = p[32 + lane];
        dst[32 + lane] = pack_fp8x4(u);
        s += u.x * u.x + u.y * u.y + u.z * u.z + u.w * u.w;
    }
    #pragma unroll
    for (int o = 16; o; o >>= 1) s += __shfl_xor_sync(0xffffffffu, s, o);
    if (lane == 0) g_y2[row] = s;
}

// ---------------- prep 2: M^T 64-address blocks, fp16, ones row at c=10 ----------------
__global__ void prep_mt_kernel(const float* __restrict__ M) {
    __shared__ float tile[64 * CDIM];
    int t = threadIdx.x;                 // 128 threads, block = 64 addresses
    size_t base = (size_t)blockIdx.x * 64 * CDIM;
    #pragma unroll
    for (int i = 0; i < 5; i++) tile[t + i * 128] = M[base + t + i * 128];
    __syncthreads();
    __half* out = g_mt + (size_t)blockIdx.x * 16 * 64;
    #pragma unroll
    for (int i = 0; i < 8; i++) {
        int idx = t + i * 128;           // c*64 + a
        int c = idx >> 6, a = idx & 63;
        float v = (c < CDIM) ? tile[a * CDIM + c] : (c == CDIM ? 1.0f : 0.0f);
        out[idx] = __float2half(v);
    }
}

// ---------------- chunk loader: fp8 B rows + fp16 M^T block (3 buffers) ----------------
__device__ __forceinline__ void issue_chunk(int c, int t, uint32_t sbase, int blkBase) {
    int buf = c % 3;
    int aBlk = blkBase + c;
    int r = t >> 2, q = t & 3;
    const char* src = (const char*)(g_ad8 + (size_t)(aBlk * 64 + r) * FD);
    uint32_t bdst = sbase + SM_B + buf * B_BUF + r * RSB;
    #pragma unroll
    for (int j = q; j < 10; j += 4)
        cp16(bdst + j * 16, src + j * 16);
    if (t < MT_BUF / 16)
        cp16(sbase + SM_MT + buf * MT_BUF + t * 16,
             (const char*)(g_mt + (size_t)aBlk * 16 * 64) + t * 16);
}

// ---------------- main fused kernel ----------------
__global__ __launch_bounds__(THREADS, 2)
void fused_mma_kernel(const float* __restrict__ X) {
    extern __shared__ __align__(1024) char sm[];
    uint32_t sbase = smem_u32(sm);
    const float* y2s = (const float*)(sm + SM_Y2);

    int t = threadIdx.x;
    int wid = t >> 5, lane = t & 31;
    int g = lane >> 2, tig = lane & 3;
    int wm = wid & 3, wn = wid >> 2;     // 4 x 2 warp grid
    int m0 = wm * 32, n0 = wn * 32;
    int rowBase = blockIdx.x * BM;
    int aSlice = blockIdx.y * APS;
    int blkBase = blockIdx.y * NCH;

    // stage A tile as e4m3
    {
        int r = t >> 1, h = t & 1;
        const float4* src = (const float4*)(X + (size_t)(rowBase + r) * FD) + h * 20;
        uint32_t adst = sbase + SM_A + r * RSB + h * 80;
        #pragma unroll
        for (int i = 0; i < 20; i++) {
            uint32_t w = pack_fp8x4(src[i]);
            asm volatile("st.shared.b32 [%0], %1;" :: "r"(adst + i * 4), "r"(w));
        }
    }
    // stage y2 slice
    cp16(sbase + SM_Y2 + t * 16, (const char*)(g_y2 + aSlice) + t * 16);
    // x2 per row (exact fp32)
    if (t < BM) {
        const float4* p = (const float4*)(X + (size_t)(rowBase + t) * FD);
        float s = 0.f;
        #pragma unroll
        for (int i = 0; i < FD / 4; i++) {
            float4 v = p[i];
            s = fmaf(v.x, v.x, s); s = fmaf(v.y, v.y, s);
            s = fmaf(v.z, v.z, s); s = fmaf(v.w, v.w, s);
        }
        ((float*)(sm + SM_X2))[t] = s;
    }
    issue_chunk(0, t, sbase, blkBase);
    cp_commit();
    cp_wait0();
    __syncthreads();

    float x2r[4];
    #pragma unroll
    for (int i = 0; i < 4; i++) x2r[i] = ((const float*)(sm + SM_X2))[m0 + g + 8 * i];

    // QK ldmatrix addresses
    int tr = lane & 7, tt = lane >> 3;
    uint32_t aBase0 = sbase + SM_A + (m0 + (tt & 1) * 8 + tr) * RSB + (tt >> 1) * 16;
    uint32_t aBase1 = aBase0 + 16 * RSB;
    uint32_t bOff0 = (n0 + (tt & 1) * 8 + tr) * RSB + (tt >> 1) * 16;
    uint32_t bOff1 = bOff0 + 16 * RSB;
    uint32_t mtOff = ((tt & 1) * 8 + tr) * 128 + (n0 + (tt >> 1) * 8) * 2;

    // persistent output accumulators
    float d_[2][2][4];
    #pragma unroll
    for (int i = 0; i < 2; i++)
        #pragma unroll
        for (int j = 0; j < 2; j++)
            #pragma unroll
            for (int k = 0; k < 4; k++) d_[i][j][k] = 0.f;

    for (int ch = 0; ch < NCH; ch++) {
        if (ch + 1 < NCH) {
            issue_chunk(ch + 1, t, sbase, blkBase);
            cp_commit();
            cp_wait1();
        } else {
            cp_wait0();
        }
        __syncthreads();   // single barrier per chunk (3-buffer WAR proof in analysis)

        uint32_t bBase = sbase + SM_B + (ch % 3) * B_BUF;

        float c_[8][4];
        #pragma unroll
        for (int i = 0; i < 8; i++)
            #pragma unroll
            for (int j = 0; j < 4; j++) c_[i][j] = 0.f;

        #pragma unroll
        for (int ks = 0; ks < FD / 32; ks++) {
            uint32_t a0[4], a1[4], b0[4], b1[4];
            ldsm4(a0, aBase0 + ks * 32);
            ldsm4(a1, aBase1 + ks * 32);
            ldsm4(b0, bBase + bOff0 + ks * 32);
            ldsm4(b1, bBase + bOff1 + ks * 32);
            mma32(c_[0], a0, b0[0], b0[2]);   mma32(c_[1], a0, b0[1], b0[3]);
            mma32(c_[2], a0, b1[0], b1[2]);   mma32(c_[3], a0, b1[1], b1[3]);
            mma32(c_[4], a1, b0[0], b0[2]);   mma32(c_[5], a1, b0[1], b0[3]);
            mma32(c_[6], a1, b1[0], b1[2]);   mma32(c_[7], a1, b1[1], b1[3]);
        }

        // ---- weights: arg = CK12 - KK*dist (f32) -> f16x2 -> ex2.f16x2 = A-frags ----
        uint32_t aP[2][2][4];    // [mb][kstep16][4]
        #pragma unroll
        for (int mb = 0; mb < 2; mb++) {
            #pragma unroll
            for (int nb = 0; nb < 4; nb++) {
                const float2 y2v = *(const float2*)(y2s + ch * BN + n0 + 8 * nb + 2 * tig);
                float arg[4];
                #pragma unroll
                for (int h = 0; h < 2; h++) {
                    #pragma unroll
                    for (int c2 = 0; c2 < 2; c2++) {
                        float d = c_[mb * 4 + nb][h * 2 + c2];
                        float q = fmaxf(fmaf(-2.f, d,
                                        x2r[2 * mb + h] + (c2 ? y2v.y : y2v.x)), 1e-12f);
                        arg[h * 2 + c2] = fmaf(sqrt_ap(q), -KK, CK12);
                    }
                }
                int ks = nb >> 1, kh = nb & 1;
                aP[mb][ks][kh * 2 + 0] = ex2_h2(pack_h2(arg[0], arg[1]));  // row g
                aP[mb][ks][kh * 2 + 1] = ex2_h2(pack_h2(arg[2], arg[3]));  // row g+8
            }
        }

        // ---- P @ M_T (fp16) ----
        {
            uint32_t mtb = sbase + SM_MT + (ch % 3) * MT_BUF + mtOff;
            uint32_t bm0[4], bm1[4];
            ldsm4(bm0, mtb);
            ldsm4(bm1, mtb + 32);
            #pragma unroll
            for (int mb = 0; mb < 2; mb++) {
                mma16h(d_[mb][0], aP[mb][0], bm0[0], bm0[2]);
                mma16h(d_[mb][1], aP[mb][0], bm0[1], bm0[3]);
                mma16h(d_[mb][0], aP[mb][1], bm1[0], bm1[2]);
                mma16h(d_[mb][1], aP[mb][1], bm1[1], bm1[3]);
            }
        }
    }

    // write partials
    {
        float* base = g_part + (size_t)(blockIdx.y * 2 + wn) * NROWS * 12;
        #pragma unroll
        for (int mb = 0; mb < 2; mb++) {
            #pragma unroll
            for (int no = 0; no < 2; no++) {
                #pragma unroll
                for (int h = 0; h < 2; h++) {
                    #pragma unroll
                    for (int c2 = 0; c2 < 2; c2++) {
                        int c = 8 * no + 2 * tig + c2;
                        if (c <= 10) {
                            int grow = rowBase + m0 + 16 * mb + 8 * h + g;
                            base[(size_t)grow * 12 + c] = d_[mb][no][2 * h + c2];
                        }
                    }
                }
            }
        }
    }
}

// ---------------- finalize ----------------
__global__ void finalize_kernel(float* __restrict__ out) {
    int idx = blockIdx.x * blockDim.x + threadIdx.x;
    if (idx >= NROWS * CDIM) return;
    int n = idx / CDIM;
    int c = idx - n * CDIM;
    float num = 0.f, den = 0.f;
    #pragma unroll
    for (int s = 0; s < SLICES * 2; s++) {
        const float* p = g_part + ((size_t)s * NROWS + n) * 12;
        num += p[c];
        den += p[10];
    }
    out[idx] = num / den;
}

extern "C" void kernel_launch(void* const* d_in, const int* in_sizes, int n_in,
                              void* d_out, int out_size) {
    const float* X  = (const float*)d_in[0];   // inputs  [4096, 160]
    const float* Ad = (const float*)d_in[1];   // Address [32768, 160]
    const float* M  = (const float*)d_in[2];   // M       [32768, 10]
    float* out = (float*)d_out;                // [4096, 10]

    cudaFuncSetAttribute(fused_mma_kernel,
                         cudaFuncAttributeMaxDynamicSharedMemorySize, SMEM_TOTAL);

    prep_kernel<<<AADDR / 8, 256>>>(Ad);
    prep_mt_kernel<<<AADDR / 64, 128>>>(M);
    fused_mma_kernel<<<dim3(NROWS / BM, SLICES), THREADS, SMEM_TOTAL>>>(X);
    finalize_kernel<<<(NROWS * CDIM + 255) / 256, 256>>>(out);
}